// round 9
// baseline (speedup 1.0000x reference)
#include <cuda_runtime.h>
#include <cuda_fp16.h>

// Problem shape (fixed by the dataset):
//   A: [32, 4096, 64] f32, B: [32, 64, 4096] f32, index: [32, 4096, 32] i32
//   C[b,m,t] = sum_k A[b,m,k] * B[b,k,index[b,m,t]]
#define BB   32
#define MDIM 4096
#define KDIM 64
#define NDIM 4096
#define TOPK 32
#define NTILE 64
#define MPB  8                     // m-rows per tile (1 per warp)
#define TILES_PER_B (MDIM / MPB)   // 512
#define NTILES (TILES_PER_B * BB)  // 16384
#define GRID_PERS 888              // 148 SMs x 6 resident blocks

// 16 MB scratch: transposed B in fp16. Bt16[b][n][k] — one gathered row is
// 64 halves = 128 B = exactly one L1 line (1 wavefront per gather group).
__device__ __half2 g_Bt16[(size_t)BB * NDIM * (KDIM / 2)];

// ---------------------------------------------------------------------------
// Kernel 1: transpose+convert B[b,k,n] f32 -> Bt16[b,n,k] fp16.
// 64x64 tiles; each thread emits one 16B (8-half) chunk via STG.128.
// grid: (NDIM/64, BB), block: (32, 16)
// ---------------------------------------------------------------------------
__global__ void __launch_bounds__(512) transpose_kernel(const float* __restrict__ B) {
    __shared__ float tile[KDIM][NTILE + 1];   // 64 x 65 floats
    const int b  = blockIdx.y;
    const int n0 = blockIdx.x * NTILE;
    const int tx = threadIdx.x;        // 0..31
    const int ty = threadIdx.y;        // 0..15

    const float* Bb = B + (size_t)b * KDIM * NDIM;
    #pragma unroll
    for (int k = ty; k < KDIM; k += 16) {
        tile[k][tx]      = Bb[(size_t)k * NDIM + n0 + tx];        // coalesced
        tile[k][tx + 32] = Bb[(size_t)k * NDIM + n0 + tx + 32];
    }
    __syncthreads();

    const int tid = ty * 32 + tx;      // 0..511
    const int row = tid >> 3;          // 0..63  (n within tile)
    const int c   = tid & 7;           // 16B chunk: k = 8c..8c+7
    uint4 out;
    __half2* o2 = reinterpret_cast<__half2*>(&out);
    #pragma unroll
    for (int i = 0; i < 4; i++)
        o2[i] = __floats2half2_rn(tile[8 * c + 2 * i][row], tile[8 * c + 2 * i + 1][row]);

    // warp writes 4 consecutive 128B rows = 512B contiguous
    __half2* dst = g_Bt16 + (size_t)b * NDIM * 32 + (size_t)(n0 + row) * 32;
    reinterpret_cast<uint4*>(dst)[c] = out;
}

// ---------------------------------------------------------------------------
// Kernel 2: gather + dot. Persistent grid-stride over 16384 tiles of 8 m
// (one m per warp). Lane layout: g = lane>>3 (4 groups, one t per chunk),
// j = lane&7 (8 lanes read one gathered 128B fp16 row: 1 LDG.128 each).
// Inner product in half2 (HFMA2), f32 cross-lane reduce; results staged in
// smem, then one coalesced 1KB block store per tile.
// grid: 888, block: 256
// ---------------------------------------------------------------------------
__global__ void __launch_bounds__(256, 6) gather_dot_kernel(
    const float* __restrict__ A,
    const int*   __restrict__ index,
    float*       __restrict__ C)
{
    __shared__ float sres[MPB][TOPK];   // 1 KB, [m_local][t]

    const int warp = threadIdx.x >> 5;
    const int lane = threadIdx.x & 31;
    const int j    = lane & 7;
    const int g    = lane >> 3;

    for (int tile = blockIdx.x; tile < NTILES; tile += GRID_PERS) {
        const int b  = tile >> 9;          // tile / TILES_PER_B
        const int mt = tile & (TILES_PER_B - 1);
        const int m  = mt * MPB + warp;

        const __half2* BtB = g_Bt16 + (size_t)b * NDIM * (KDIM / 2);

        // A row: lane j holds floats [8j, 8j+8), converted to half2 once
        const float4* A4 = reinterpret_cast<const float4*>(A + ((size_t)b * MDIM + m) * KDIM);
        const float4 a0 = __ldg(&A4[2 * j]);
        const float4 a1 = __ldg(&A4[2 * j + 1]);
        const __half2 ah0 = __floats2half2_rn(a0.x, a0.y);
        const __half2 ah1 = __floats2half2_rn(a0.z, a0.w);
        const __half2 ah2 = __floats2half2_rn(a1.x, a1.y);
        const __half2 ah3 = __floats2half2_rn(a1.z, a1.w);

        // lane t holds index for t; broadcast per chunk via shfl
        const int myidx = __ldg(&index[((size_t)b * MDIM + m) * TOPK + lane]);

        float* srow = sres[warp];

        #pragma unroll
        for (int t0 = 0; t0 < TOPK; t0 += 4) {
            const int idxv = __shfl_sync(0xffffffffu, myidx, t0 + g);
            // gathered row = 128 B; lane j reads its 16B slice (8 halves)
            const uint4 bv = __ldg(&reinterpret_cast<const uint4*>(BtB + (size_t)idxv * 32)[j]);

            __half2 acc =       __hmul2(ah0, *reinterpret_cast<const __half2*>(&bv.x));
            acc = __hfma2(ah1, *reinterpret_cast<const __half2*>(&bv.y), acc);
            acc = __hfma2(ah2, *reinterpret_cast<const __half2*>(&bv.z), acc);
            acc = __hfma2(ah3, *reinterpret_cast<const __half2*>(&bv.w), acc);

            const float2 f = __half22float2(acc);
            float p = f.x + f.y;

            // reduce over the 8 lanes of each group (xor keeps it intra-group)
            p += __shfl_xor_sync(0xffffffffu, p, 1);
            p += __shfl_xor_sync(0xffffffffu, p, 2);
            p += __shfl_xor_sync(0xffffffffu, p, 4);

            if (j == 0) srow[t0 + g] = p;   // 4 lanes, 4 consecutive banks
        }
        __syncthreads();

        // Tile's C chunk: 8 m x 32 t = 256 floats contiguous, 1 STG per thread.
        float* dst = C + ((size_t)b * MDIM + (size_t)mt * MPB) * TOPK;
        dst[threadIdx.x] = reinterpret_cast<const float*>(sres)[threadIdx.x];
        __syncthreads();   // protect sres before next tile overwrites it
    }
}

// ---------------------------------------------------------------------------
extern "C" void kernel_launch(void* const* d_in, const int* in_sizes, int n_in,
                              void* d_out, int out_size) {
    const float* A   = (const float*)d_in[0];
    const float* B   = (const float*)d_in[1];
    const int*   idx = (const int*)d_in[2];
    float*       C   = (float*)d_out;

    transpose_kernel<<<dim3(NDIM / NTILE, BB), dim3(32, 16)>>>(B);
    gather_dot_kernel<<<GRID_PERS, 256>>>(A, idx, C);
}

// round 10
// speedup vs baseline: 1.0699x; 1.0699x over previous
#include <cuda_runtime.h>
#include <cuda_fp16.h>

// Problem shape (fixed by the dataset):
//   A: [32, 4096, 64] f32, B: [32, 64, 4096] f32, index: [32, 4096, 32] i32
//   C[b,m,t] = sum_k A[b,m,k] * B[b,k,index[b,m,t]]
#define BB   32
#define MDIM 4096
#define KDIM 64
#define NDIM 4096
#define TOPK 32
#define NTILE 64
#define GRID_PERS 888                    // 148 SMs x 6 resident blocks
#define NWARPS   (GRID_PERS * 8)         // 7104 persistent warps
#define TOTAL_M  (BB * MDIM)             // 131072

// 16 MB scratch: transposed B in fp16. Bt16[b][n][k] — one gathered row is
// 64 halves = 128 B = exactly one L1 line (1 wavefront per gather group).
__device__ __half2 g_Bt16[(size_t)BB * NDIM * (KDIM / 2)];

// ---------------------------------------------------------------------------
// Kernel 1: transpose+convert B[b,k,n] f32 -> Bt16[b,n,k] fp16.
// 64x64 tiles; each thread emits one 16B (8-half) chunk via STG.128.
// grid: (NDIM/64, BB), block: (32, 16)
// ---------------------------------------------------------------------------
__global__ void __launch_bounds__(512) transpose_kernel(const float* __restrict__ B) {
    __shared__ float tile[KDIM][NTILE + 1];   // 64 x 65 floats
    const int b  = blockIdx.y;
    const int n0 = blockIdx.x * NTILE;
    const int tx = threadIdx.x;        // 0..31
    const int ty = threadIdx.y;        // 0..15

    const float* Bb = B + (size_t)b * KDIM * NDIM;
    #pragma unroll
    for (int k = ty; k < KDIM; k += 16) {
        tile[k][tx]      = Bb[(size_t)k * NDIM + n0 + tx];        // coalesced
        tile[k][tx + 32] = Bb[(size_t)k * NDIM + n0 + tx + 32];
    }
    __syncthreads();

    const int tid = ty * 32 + tx;      // 0..511
    const int row = tid >> 3;          // 0..63  (n within tile)
    const int c   = tid & 7;           // 16B chunk: k = 8c..8c+7
    uint4 out;
    __half2* o2 = reinterpret_cast<__half2*>(&out);
    #pragma unroll
    for (int i = 0; i < 4; i++)
        o2[i] = __floats2half2_rn(tile[8 * c + 2 * i][row], tile[8 * c + 2 * i + 1][row]);

    // warp writes 4 consecutive 128B rows = 512B contiguous
    __half2* dst = g_Bt16 + (size_t)b * NDIM * 32 + (size_t)(n0 + row) * 32;
    reinterpret_cast<uint4*>(dst)[c] = out;
}

// ---------------------------------------------------------------------------
// Kernel 2: gather + dot. Warp-persistent: each warp grid-strides over single
// m-rows (no barriers, no smem). Lane layout: g = lane>>3 (4 groups, one t
// per chunk), j = lane&7 (8 lanes read one gathered 128B fp16 row: 1 LDG.128
// each). Inner product in half2 (HFMA2), f32 xor-reduce puts p on ALL lanes;
// lane l keeps iteration i == (l&7), i.e. t = 4*(l&7) + (l>>3) — a bijection
// on 0..31 — then one permuted-within-line STG.32 per m (1 wavefront).
// grid: 888, block: 256
// ---------------------------------------------------------------------------
__global__ void __launch_bounds__(256, 6) gather_dot_kernel(
    const float* __restrict__ A,
    const int*   __restrict__ index,
    float*       __restrict__ C)
{
    const int warp = threadIdx.x >> 5;
    const int lane = threadIdx.x & 31;
    const int j    = lane & 7;
    const int g    = lane >> 3;
    const int keep_i  = j;                       // iteration this lane keeps
    const int t_store = 4 * j + g;               // t this lane stores

    const int w0 = blockIdx.x * 8 + warp;        // global warp id

    for (int mi = w0; mi < TOTAL_M; mi += NWARPS) {
        const int b = mi >> 12;                  // mi / MDIM
        const int m = mi & (MDIM - 1);

        const __half2* BtB = g_Bt16 + (size_t)b * NDIM * (KDIM / 2);

        // A row: lane j holds floats [8j, 8j+8), converted to half2 once
        const float4* A4 = reinterpret_cast<const float4*>(A + ((size_t)b * MDIM + m) * KDIM);
        const float4 a0 = __ldg(&A4[2 * j]);
        const float4 a1 = __ldg(&A4[2 * j + 1]);
        const __half2 ah0 = __floats2half2_rn(a0.x, a0.y);
        const __half2 ah1 = __floats2half2_rn(a0.z, a0.w);
        const __half2 ah2 = __floats2half2_rn(a1.x, a1.y);
        const __half2 ah3 = __floats2half2_rn(a1.z, a1.w);

        // lane t holds index for t; broadcast per chunk via shfl
        const int myidx = __ldg(&index[((size_t)b * MDIM + m) * TOPK + lane]);

        float keep = 0.0f;

        #pragma unroll
        for (int i = 0; i < 8; i++) {
            const int idxv = __shfl_sync(0xffffffffu, myidx, 4 * i + g);
            // gathered row = 128 B; lane j reads its 16B slice (8 halves)
            const uint4 bv = __ldg(&reinterpret_cast<const uint4*>(BtB + (size_t)idxv * 32)[j]);

            __half2 acc =       __hmul2(ah0, *reinterpret_cast<const __half2*>(&bv.x));
            acc = __hfma2(ah1, *reinterpret_cast<const __half2*>(&bv.y), acc);
            acc = __hfma2(ah2, *reinterpret_cast<const __half2*>(&bv.z), acc);
            acc = __hfma2(ah3, *reinterpret_cast<const __half2*>(&bv.w), acc);

            const float2 f = __half22float2(acc);
            float p = f.x + f.y;

            // xor-reduce over the 8 lanes of each group: p valid on ALL lanes
            p += __shfl_xor_sync(0xffffffffu, p, 1);
            p += __shfl_xor_sync(0xffffffffu, p, 2);
            p += __shfl_xor_sync(0xffffffffu, p, 4);

            if (i == keep_i) keep = p;           // predicated SEL
        }

        // one 128B line, permuted within line: 1 store wavefront per m
        C[((size_t)b * MDIM + m) * TOPK + t_store] = keep;
    }
}

// ---------------------------------------------------------------------------
extern "C" void kernel_launch(void* const* d_in, const int* in_sizes, int n_in,
                              void* d_out, int out_size) {
    const float* A   = (const float*)d_in[0];
    const float* B   = (const float*)d_in[1];
    const int*   idx = (const int*)d_in[2];
    float*       C   = (float*)d_out;

    transpose_kernel<<<dim3(NDIM / NTILE, BB), dim3(32, 16)>>>(B);
    gather_dot_kernel<<<GRID_PERS, 256>>>(A, idx, C);
}

// round 11
// speedup vs baseline: 1.2604x; 1.1780x over previous
#include <cuda_runtime.h>
#include <cuda_fp16.h>

// Problem shape (fixed by the dataset):
//   A: [32, 4096, 64] f32, B: [32, 64, 4096] f32, index: [32, 4096, 32] i32
//   C[b,m,t] = sum_k A[b,m,k] * B[b,k,index[b,m,t]]
#define BB   32
#define MDIM 4096
#define KDIM 64
#define NDIM 4096
#define TOPK 32
#define NTILE 64
#define GRID_PERS 888                    // 148 SMs x 6 blocks
#define NWARPS   (GRID_PERS * 8)         // 7104 persistent warps
#define TOTAL_M  (BB * MDIM)             // 131072

// 16 MB scratch: transposed B in fp16. Bt16[b][n][k] — one gathered row is
// 64 halves = 128 B = exactly one L1 line (1 wavefront per gather group).
__device__ __half2 g_Bt16[(size_t)BB * NDIM * (KDIM / 2)];

// ---------------------------------------------------------------------------
// Kernel 1: transpose+convert B[b,k,n] f32 -> Bt16[b,n,k] fp16.
// 64x64 tiles; each thread emits one 16B (8-half) chunk via STG.128.
// grid: (NDIM/64, BB), block: (32, 16)
// ---------------------------------------------------------------------------
__global__ void __launch_bounds__(512) transpose_kernel(const float* __restrict__ B) {
    __shared__ float tile[KDIM][NTILE + 1];   // 64 x 65 floats
    const int b  = blockIdx.y;
    const int n0 = blockIdx.x * NTILE;
    const int tx = threadIdx.x;        // 0..31
    const int ty = threadIdx.y;        // 0..15

    const float* Bb = B + (size_t)b * KDIM * NDIM;
    #pragma unroll
    for (int k = ty; k < KDIM; k += 16) {
        tile[k][tx]      = Bb[(size_t)k * NDIM + n0 + tx];        // coalesced
        tile[k][tx + 32] = Bb[(size_t)k * NDIM + n0 + tx + 32];
    }
    __syncthreads();

    const int tid = ty * 32 + tx;      // 0..511
    const int row = tid >> 3;          // 0..63  (n within tile)
    const int c   = tid & 7;           // 16B chunk: k = 8c..8c+7
    uint4 out;
    __half2* o2 = reinterpret_cast<__half2*>(&out);
    #pragma unroll
    for (int i = 0; i < 4; i++)
        o2[i] = __floats2half2_rn(tile[8 * c + 2 * i][row], tile[8 * c + 2 * i + 1][row]);

    // warp writes 4 consecutive 128B rows = 512B contiguous
    __half2* dst = g_Bt16 + (size_t)b * NDIM * 32 + (size_t)(n0 + row) * 32;
    reinterpret_cast<uint4*>(dst)[c] = out;
}

// ---------------------------------------------------------------------------
// Kernel 2: gather + dot. Warp-persistent, barrier-free, smem-free.
// Lane layout: g = lane>>3 (4 groups), j = lane&7 (8 lanes read one gathered
// 128B fp16 row: 1 LDG.128 each). Iteration i computes t = 4i+g; each lane
// holds its j-slice partial p[i] (fp16 HFMA2 chain, f32 pair-sum). After the
// loop a 3-round butterfly (XOR 1,2,4) transposes+reduces: lane (g,j) ends
// with the full sum for i=j, i.e. t = 4j+g — same summation tree as a
// per-iteration xor-reduce, so results are bit-identical to R8/R10.
// grid: 888, block: 256
// ---------------------------------------------------------------------------
__global__ void __launch_bounds__(256) gather_dot_kernel(
    const float* __restrict__ A,
    const int*   __restrict__ index,
    float*       __restrict__ C)
{
    const int warp = threadIdx.x >> 5;
    const int lane = threadIdx.x & 31;
    const int j    = lane & 7;
    const int g    = lane >> 3;
    const int t_store = 4 * j + g;               // bijection on 0..31

    const int w0 = blockIdx.x * 8 + warp;        // global warp id

    for (int mi = w0; mi < TOTAL_M; mi += NWARPS) {
        const int b = mi >> 12;                  // mi / MDIM
        const int m = mi & (MDIM - 1);

        const char* BtB = reinterpret_cast<const char*>(g_Bt16 + (size_t)b * NDIM * (KDIM / 2));

        // A row: lane j holds floats [8j, 8j+8), converted to half2 once
        const float4* A4 = reinterpret_cast<const float4*>(A + ((size_t)b * MDIM + m) * KDIM);
        const float4 a0 = __ldg(&A4[2 * j]);
        const float4 a1 = __ldg(&A4[2 * j + 1]);
        const __half2 ah0 = __floats2half2_rn(a0.x, a0.y);
        const __half2 ah1 = __floats2half2_rn(a0.z, a0.w);
        const __half2 ah2 = __floats2half2_rn(a1.x, a1.y);
        const __half2 ah3 = __floats2half2_rn(a1.z, a1.w);

        // lane t holds byte offset of row index[t] (pre-scaled: saves IMADs)
        const int myoff = __ldg(&index[((size_t)b * MDIM + m) * TOPK + lane]) * 128;

        float p[8];

        #pragma unroll
        for (int i = 0; i < 8; i++) {
            const int offv = __shfl_sync(0xffffffffu, myoff, 4 * i + g);
            // gathered row = 128 B; lane j reads its 16B slice (8 halves)
            const uint4 bv = __ldg(reinterpret_cast<const uint4*>(BtB + offv) + j);

            __half2 acc =       __hmul2(ah0, *reinterpret_cast<const __half2*>(&bv.x));
            acc = __hfma2(ah1, *reinterpret_cast<const __half2*>(&bv.y), acc);
            acc = __hfma2(ah2, *reinterpret_cast<const __half2*>(&bv.z), acc);
            acc = __hfma2(ah3, *reinterpret_cast<const __half2*>(&bv.w), acc);

            const float2 f = __half22float2(acc);
            p[i] = f.x + f.y;
        }

        // Butterfly transpose-reduce over the 8-lane group.
        // Round 1 (XOR 1): keep registers i with bit0(i)==bit0(j).
        const int ja = j & 1, jb = (j >> 1) & 1, jc = (j >> 2) & 1;
        float q[4];
        #pragma unroll
        for (int d = 0; d < 4; d++) {
            const float give = ja ? p[2 * d] : p[2 * d + 1];
            const float keep = ja ? p[2 * d + 1] : p[2 * d];
            q[d] = keep + __shfl_xor_sync(0xffffffffu, give, 1);
        }   // q[d] ~ i = 2d + ja
        // Round 2 (XOR 2): keep d with bit0(d)==bit1(j).
        float r0, r1;
        {
            const float give0 = jb ? q[0] : q[1];
            const float keep0 = jb ? q[1] : q[0];
            r0 = keep0 + __shfl_xor_sync(0xffffffffu, give0, 2);   // i = 2jb + ja
            const float give1 = jb ? q[2] : q[3];
            const float keep1 = jb ? q[3] : q[2];
            r1 = keep1 + __shfl_xor_sync(0xffffffffu, give1, 2);   // i = 4 + 2jb + ja
        }
        // Round 3 (XOR 4): keep r with bit2(i)==bit2(j).
        const float give = jc ? r0 : r1;
        const float keep = jc ? r1 : r0;
        const float total = keep + __shfl_xor_sync(0xffffffffu, give, 4);
        // lane now holds i = 4jc + 2jb + ja = j  ->  t = 4j + g = t_store

        // one 128B line, permuted within line: 1 store wavefront per m
        C[((size_t)b * MDIM + m) * TOPK + t_store] = total;
    }
}

// ---------------------------------------------------------------------------
extern "C" void kernel_launch(void* const* d_in, const int* in_sizes, int n_in,
                              void* d_out, int out_size) {
    const float* A   = (const float*)d_in[0];
    const float* B   = (const float*)d_in[1];
    const int*   idx = (const int*)d_in[2];
    float*       C   = (float*)d_out;

    transpose_kernel<<<dim3(NDIM / NTILE, BB), dim3(32, 16)>>>(B);
    gather_dot_kernel<<<GRID_PERS, 256>>>(A, idx, C);
}